// round 15
// baseline (speedup 1.0000x reference)
#include <cuda_runtime.h>
#include <cuda_fp16.h>
#include <cstdint>

// Problem constants
#define Bn 131072
#define Cn 128
#define En 128
#define TM 128              // samples per tile
#define NTILES (Bn / TM)    // 1024
#define NPERS 296           // persistent CTAs (2 per SM on 148 SMs)

// ArcFace constants (m = 1.0, s = 100)
#define COSM 0.5403023058681398f
#define SINM 0.8414709848078965f
#define THv  (-0.5403023058681398f)
#define MMv  0.8414709848078965f
#define Sv   100.0f
#define SHIFT 30.0f
#define LOG2E 1.4426950408889634f
#define SH2   (SHIFT * LOG2E)

// Scratch (no allocation allowed -> device globals)
__device__ uint32_t g_wfrag[8192];   // 32KB: normalized weight fp16, fragment order
__device__ float    g_bsum[NPERS];
__device__ int      g_cnt;           // zero-init; reset by last CTA each launch
__device__ int      g_ready;         // weight-prep release counter (16 CTAs)

// smem layout (bytes)
#define OFF_A0   0                   // A buffer 0: half[128][136] -> 34816
#define OFF_A1   34816               // A buffer 1                 -> 34816
#define OFF_B    69632               // B fragments, 512 x 80B     -> 40960
#define OFF_INV  110592              // float[2][128]              -> 1024
#define OFF_LBL  111616              // int[2][128]                -> 1024
#define OFF_RED  112640              // float[8]
#define OFF_FLAG 112672              // int
#define SMEM_SZ  112688

__device__ __forceinline__ float ex2(float x) {
    float r; asm("ex2.approx.f32 %0, %1;" : "=f"(r) : "f"(x)); return r;
}

__device__ __forceinline__ void hmma16816(float& c0, float& c1, float& c2, float& c3,
                                          uint32_t a0, uint32_t a1, uint32_t a2, uint32_t a3,
                                          uint32_t b0, uint32_t b1) {
    asm volatile(
        "mma.sync.aligned.m16n8k16.row.col.f32.f16.f16.f32 "
        "{%0,%1,%2,%3}, {%4,%5,%6,%7}, {%8,%9}, {%0,%1,%2,%3};"
        : "+f"(c0), "+f"(c1), "+f"(c2), "+f"(c3)
        : "r"(a0), "r"(a1), "r"(a2), "r"(a3), "r"(b0), "r"(b1));
}

// NLL from label-EXCLUDED shifted sum se = sum exp(z-30), and label cosine cs.
__device__ __forceinline__ float row_nll(float se, float cs) {
    float sn  = sqrtf(fmaxf(1.0f - cs * cs, 0.0f));
    float phi = (cs > THv) ? (cs * COSM - sn * SINM) : (cs - MMv);
    float zl  = Sv * phi;
    float se2 = se + ex2(fmaf(zl, LOG2E, -SH2));
    return (SHIFT + __logf(se2)) - zl;
}

// prefetch 8 rows of predict+target into registers (R12-validated)
__device__ __forceinline__ void issue_half(const float* __restrict__ predict,
                                           const float* __restrict__ target,
                                           int tile, int rowLocal, int lane,
                                           float4* Vp, float4* Vt)
{
    const size_t base = ((size_t)tile * TM + rowLocal) * 32 + lane;
    const float4* p4 = (const float4*)predict;
    const float4* t4 = (const float4*)target;
    #pragma unroll
    for (int j = 0; j < 8; j++) {
        Vp[j] = __ldg(p4 + base + (size_t)j * 32);
        Vt[j] = __ldg(t4 + base + (size_t)j * 32);
    }
}

// process 8 prefetched rows: fp16 convert + STS; ssq butterfly; ballot label;
// write per-row invn + label to smem arrays (producer-side)
__device__ __forceinline__ void proc_chunk(const float4* Vp, const float4* Vt,
                                           char* sAbuf, int rowLocal, int lane, int g, int c,
                                           float* sInv, int* sLbl)
{
    float ssq[8]; int lbl = 0;
    #pragma unroll
    for (int j = 0; j < 8; j++) {
        float4 v = Vp[j], t = Vt[j];
        __half2 h0 = __floats2half2_rn(v.x, v.y);
        __half2 h1 = __floats2half2_rn(v.z, v.w);
        unsigned long long pk;
        asm("mov.b64 %0,{%1,%2};" : "=l"(pk)
            : "r"(*(uint32_t*)&h0), "r"(*(uint32_t*)&h1));
        *reinterpret_cast<unsigned long long*>(sAbuf + (rowLocal + j) * 272 + lane * 8) = pk;
        ssq[j] = fmaf(v.x, v.x, fmaf(v.y, v.y, fmaf(v.z, v.z, v.w * v.w)));

        bool nz = (t.x > 0.5f) || (t.y > 0.5f) || (t.z > 0.5f) || (t.w > 0.5f);
        unsigned bal = __ballot_sync(0xffffffffu, nz);
        int li = (t.y > 0.5f) ? 1 : ((t.z > 0.5f) ? 2 : ((t.w > 0.5f) ? 3 : 0));
        int src = __ffs(bal) - 1;
        int lblj = 4 * src + __shfl_sync(0xffffffffu, li, src);
        if (j == g) lbl = lblj;
    }
    #pragma unroll
    for (int o = 16; o; o >>= 1) {
        #pragma unroll
        for (int i = 0; i < 8; i++) ssq[i] += __shfl_xor_sync(0xffffffffu, ssq[i], o);
    }
    float ss = 0.f;
    #pragma unroll
    for (int i = 0; i < 8; i++) if (i == g) ss = ssq[i];
    if (c == 0) {
        sInv[rowLocal + g] = rsqrtf(fmaxf(ss, 1e-24f));
        sLbl[rowLocal + g] = lbl;
    }
}

// producer: fill 32 rows (4 chunks) of one A buffer for the given tile
__device__ __forceinline__ void produce(const float* __restrict__ predict,
                                        const float* __restrict__ target,
                                        int tile, char* sAbuf, float* sInv, int* sLbl,
                                        int lane, int g, int c, int rb)
{
    float4 Vp[8], Vt[8];
    #pragma unroll
    for (int ch = 0; ch < 4; ch++) {
        issue_half(predict, target, tile, rb + 8 * ch, lane, Vp, Vt);
        proc_chunk(Vp, Vt, sAbuf, rb + 8 * ch, lane, g, c, sInv, sLbl);
    }
}

__device__ __forceinline__ void load_afrags(const char* sAbuf, int rb0, int g, int c,
                                            uint32_t* A0, uint32_t* A1,
                                            uint32_t* A2, uint32_t* A3)
{
    const char* a_lo = sAbuf + (rb0 + g) * 272 + c * 4;
    const char* a_hi = a_lo + 8 * 272;
    #pragma unroll
    for (int ks = 0; ks < 8; ks++) {
        A0[ks] = *(const uint32_t*)(a_lo + ks * 32);
        A2[ks] = *(const uint32_t*)(a_lo + ks * 32 + 16);
        A1[ks] = *(const uint32_t*)(a_hi + ks * 32);
        A3[ks] = *(const uint32_t*)(a_hi + ks * 32 + 16);
    }
}

// 8 col-tiles; B via LDS.128 fragment loads (80B lane stride, conflict-free)
__device__ __forceinline__ void mma_half(int tstart, const char* sB, int lane, int c,
    const uint32_t* A0, const uint32_t* A1, const uint32_t* A2, const uint32_t* A3,
    float sI0, float sI1, float invn0, float invn1, int lbl0, int lbl1,
    float& ac00, float& ac01, float& ac10, float& ac11, float& cs0, float& cs1)
{
    #pragma unroll
    for (int t = 0; t < 8; t++) {
        const int tt = tstart + t;
        float c0 = 0.f, c1 = 0.f, c2 = 0.f, c3 = 0.f;
        const char* bb = sB + (tt * 32 + lane) * 80;
        #pragma unroll
        for (int q = 0; q < 4; q++) {
            const uint4 bv = *(const uint4*)(bb + q * 16);
            hmma16816(c0, c1, c2, c3,
                      A0[2*q], A1[2*q], A2[2*q], A3[2*q], bv.x, bv.y);
            hmma16816(c0, c1, c2, c3,
                      A0[2*q+1], A1[2*q+1], A2[2*q+1], A3[2*q+1], bv.z, bv.w);
        }
        const int n0 = 8 * tt + 2 * c;
        float e0 = ex2(fmaf(c0, sI0, -SH2));
        float e1 = ex2(fmaf(c1, sI0, -SH2));
        float e2 = ex2(fmaf(c2, sI1, -SH2));
        float e3 = ex2(fmaf(c3, sI1, -SH2));
        if (n0     == lbl0) { cs0 = c0 * invn0; e0 = 0.f; }
        if (n0 + 1 == lbl0) { cs0 = c1 * invn0; e1 = 0.f; }
        if (n0     == lbl1) { cs1 = c2 * invn1; e2 = 0.f; }
        if (n0 + 1 == lbl1) { cs1 = c3 * invn1; e3 = 0.f; }
        ac00 += e0; ac01 += e1; ac10 += e2; ac11 += e3;
    }
}

// consumer: full arcface+softmax for 32 rows (two 16-row blocks, frags reloaded)
__device__ __forceinline__ float consume_tile(const char* sAbuf, const char* sB,
                                              const float* sInv, const int* sLbl,
                                              int lane, int g, int c, int wc)
{
    float nll = 0.f;
    #pragma unroll
    for (int h = 0; h < 2; h++) {
        const int rb0 = wc * 32 + h * 16;
        uint32_t A0[8], A1[8], A2[8], A3[8];
        load_afrags(sAbuf, rb0, g, c, A0, A1, A2, A3);
        const float invn0 = sInv[rb0 + g],     invn1 = sInv[rb0 + 8 + g];
        const int   lbl0  = sLbl[rb0 + g],     lbl1  = sLbl[rb0 + 8 + g];
        const float sI0 = Sv * invn0 * LOG2E,  sI1 = Sv * invn1 * LOG2E;
        float ac00 = 0.f, ac01 = 0.f, ac10 = 0.f, ac11 = 0.f;
        float cs0 = -2.0f, cs1 = -2.0f;

        mma_half(0, sB, lane, c, A0, A1, A2, A3, sI0, sI1, invn0, invn1, lbl0, lbl1,
                 ac00, ac01, ac10, ac11, cs0, cs1);
        mma_half(8, sB, lane, c, A0, A1, A2, A3, sI0, sI1, invn0, invn1, lbl0, lbl1,
                 ac00, ac01, ac10, ac11, cs0, cs1);

        float se0 = ac00 + ac01, se1 = ac10 + ac11;
        se0 += __shfl_xor_sync(0xffffffffu, se0, 1);
        se0 += __shfl_xor_sync(0xffffffffu, se0, 2);
        se1 += __shfl_xor_sync(0xffffffffu, se1, 1);
        se1 += __shfl_xor_sync(0xffffffffu, se1, 2);
        cs0 = fmaxf(cs0, __shfl_xor_sync(0xffffffffu, cs0, 1));
        cs0 = fmaxf(cs0, __shfl_xor_sync(0xffffffffu, cs0, 2));
        cs1 = fmaxf(cs1, __shfl_xor_sync(0xffffffffu, cs1, 1));
        cs1 = fmaxf(cs1, __shfl_xor_sync(0xffffffffu, cs1, 2));
        if (c == 0) nll += row_nll(se0, cs0) + row_nll(se1, cs1);
    }
    return nll;
}

// ---------------------------------------------------------------------------
// fused kernel: warps 0-3 produce (load/convert), warps 4-7 consume (HMMA)
// ---------------------------------------------------------------------------
__global__ void __launch_bounds__(256, 2)
arc_main(const float* __restrict__ predict,
         const float* __restrict__ target,
         const float* __restrict__ weight,
         float* __restrict__ out)
{
    extern __shared__ char sm[];
    char*  sA0  = sm + OFF_A0;
    char*  sA1  = sm + OFF_A1;
    char*  sB   = sm + OFF_B;
    float* sInv = (float*)(sm + OFF_INV);    // [2][128]
    int*   sLbl = (int*)(sm + OFF_LBL);      // [2][128]
    float* red  = (float*)(sm + OFF_RED);
    int*   flag = (int*)(sm + OFF_FLAG);

    const int tid  = threadIdx.x;
    const int lane = tid & 31;
    const int w    = tid >> 5;
    const int g    = lane >> 2;
    const int c    = lane & 3;
    const int blk  = blockIdx.x;
    const bool isProd = (w < 4);

    // ---- distributed weight prep: CTAs 0..15, one warp per weight row ----
    if (blk < 16) {
        const int row = blk * 8 + w;
        const int gg  = row & 7;
        const int tt  = row >> 3;
        float4 v = reinterpret_cast<const float4*>(weight)[row * 32 + lane];
        float ss = v.x * v.x + v.y * v.y + v.z * v.z + v.w * v.w;
        #pragma unroll
        for (int o = 16; o; o >>= 1) ss += __shfl_xor_sync(0xffffffffu, ss, o);
        float r = 1.0f / fmaxf(sqrtf(ss), 1e-12f);
        __half2 h0 = __floats2half2_rn(v.x * r, v.y * r);
        __half2 h1 = __floats2half2_rn(v.z * r, v.w * r);
        #pragma unroll
        for (int j = 0; j < 2; j++) {
            const int m  = 2 * lane + j;
            const int cc = m & 3, b = (m >> 2) & 1, ks = m >> 3;
            const int di = (tt * 32 + gg * 4 + cc) * 16 + 2 * ks + b;
            g_wfrag[di] = (j == 0) ? *(uint32_t*)&h0 : *(uint32_t*)&h1;
        }
        __threadfence();
        __syncthreads();
        if (tid == 0) atomicAdd(&g_ready, 1);
    }

    // ---- prologue: producers fill buffer 0; consumers wait + stage B ----
    if (isProd) {
        produce(predict, target, blk, sA0, sInv, sLbl, lane, g, c, w * 32);
    } else {
        if (lane == 0) {
            volatile int* gr = &g_ready;
            while (*gr < 16) { }
        }
        __syncwarp();
        const uint4* gw = (const uint4*)g_wfrag;     // 2048 uint4
        const int ct = tid - 128;
        #pragma unroll
        for (int i = 0; i < 16; i++) {
            int idx = i * 128 + ct;
            *(uint4*)(sB + (idx >> 2) * 80 + (idx & 3) * 16) = gw[idx];
        }
    }
    __syncthreads();

    // ---- pipelined main loop ----
    int tile = blk;
    int pb   = 1;          // buffer producers write next
    float nll_acc = 0.f;

    while (true) {
        const int nxt = tile + NPERS;
        if (isProd) {
            if (nxt < NTILES) {
                char*  pA = pb ? sA1 : sA0;
                float* pI = sInv + pb * 128;
                int*   pL = sLbl + pb * 128;
                produce(predict, target, nxt, pA, pI, pL, lane, g, c, w * 32);
            }
        } else {
            const int cb = pb ^ 1;
            const char*  cA = cb ? sA1 : sA0;
            nll_acc += consume_tile(cA, sB, sInv + cb * 128, sLbl + cb * 128,
                                    lane, g, c, w - 4);
        }
        __syncthreads();
        if (nxt >= NTILES) break;
        tile = nxt; pb ^= 1;
    }

    // ---- warp & block reduction of accumulated NLL (producers add 0) ----
    float nll = nll_acc;
    #pragma unroll
    for (int o = 16; o; o >>= 1) nll += __shfl_xor_sync(0xffffffffu, nll, o);
    if (lane == 0) red[w] = nll;
    __syncthreads();

    if (tid == 0) {
        float t = 0.0f;
        #pragma unroll
        for (int i = 0; i < 8; i++) t += red[i];
        g_bsum[blk] = t;
        __threadfence();
        int cdone = atomicAdd(&g_cnt, 1);
        *flag = (cdone == NPERS - 1) ? 1 : 0;
    }
    __syncthreads();

    // last CTA: deterministic final reduction -> mean; reset counters
    if (*flag) {
        __threadfence();
        float t = g_bsum[tid];
        if (tid + 256 < NPERS) t += g_bsum[tid + 256];
        float* fr = (float*)sA0;   // reuse smem
        fr[tid] = t;
        __syncthreads();
        #pragma unroll
        for (int st = 128; st; st >>= 1) {
            if (tid < st) fr[tid] += fr[tid + st];
            __syncthreads();
        }
        if (tid == 0) {
            out[0]  = fr[0] / (float)Bn;
            g_cnt   = 0;
            g_ready = 0;
        }
    }
}

// ---------------------------------------------------------------------------
extern "C" void kernel_launch(void* const* d_in, const int* in_sizes, int n_in,
                              void* d_out, int out_size)
{
    (void)in_sizes; (void)n_in; (void)out_size;
    const float* predict = (const float*)d_in[0];
    const float* target  = (const float*)d_in[1];
    const float* weight  = (const float*)d_in[2];

    cudaFuncSetAttribute(arc_main, cudaFuncAttributeMaxDynamicSharedMemorySize, SMEM_SZ);

    arc_main<<<NPERS, 256, SMEM_SZ>>>(predict, target, weight, (float*)d_out);
}

// round 16
// speedup vs baseline: 2.2292x; 2.2292x over previous
#include <cuda_runtime.h>
#include <cuda_fp16.h>
#include <cstdint>

// Problem constants
#define Bn 131072
#define Cn 128
#define En 128
#define TM 128              // samples per tile
#define NTILES (Bn / TM)    // 1024
#define NPERS 296           // persistent CTAs (2 per SM on 148 SMs)

// ArcFace constants (m = 1.0, s = 100)
#define COSM 0.5403023058681398f
#define SINM 0.8414709848078965f
#define THv  (-0.5403023058681398f)
#define MMv  0.8414709848078965f
#define Sv   100.0f
#define SHIFT 30.0f                 // exp(z-30): no overflow, no harmful underflow
#define LOG2E 1.4426950408889634f
#define SH2   (SHIFT * LOG2E)

// Scratch (no allocation allowed -> device globals)
__device__ uint32_t g_wfrag[8192];   // 32KB: normalized weight fp16, HMMA fragment order
__device__ float    g_bsum[NPERS];
__device__ int      g_cnt;           // zero-init; reset by last CTA each launch
__device__ int      g_ready;         // weight-prep release counter (16 CTAs)

// smem layout
//   A: half[128][136] rows stride 272B              -> 34816 B
//   B: fragment order, 512 lane-rows x 80B stride   -> 40960 B
#define OFF_A    0
#define OFF_B    34816
#define OFF_RED  75776               // float[8]
#define OFF_FLAG 75808               // int
#define SMEM_SZ  75840

__device__ __forceinline__ float ex2(float x) {
    float r; asm("ex2.approx.f32 %0, %1;" : "=f"(r) : "f"(x)); return r;
}

__device__ __forceinline__ void hmma16816(float& c0, float& c1, float& c2, float& c3,
                                          uint32_t a0, uint32_t a1, uint32_t a2, uint32_t a3,
                                          uint32_t b0, uint32_t b1) {
    asm volatile(
        "mma.sync.aligned.m16n8k16.row.col.f32.f16.f16.f32 "
        "{%0,%1,%2,%3}, {%4,%5,%6,%7}, {%8,%9}, {%0,%1,%2,%3};"
        : "+f"(c0), "+f"(c1), "+f"(c2), "+f"(c3)
        : "r"(a0), "r"(a1), "r"(a2), "r"(a3), "r"(b0), "r"(b1));
}

// NLL from label-EXCLUDED shifted sum se = sum exp(z-30), and label cosine cs.
__device__ __forceinline__ float row_nll(float se, float cs) {
    float sn  = sqrtf(fmaxf(1.0f - cs * cs, 0.0f));
    float phi = (cs > THv) ? (cs * COSM - sn * SINM) : (cs - MMv);
    float zl  = Sv * phi;
    float se2 = se + ex2(fmaf(zl, LOG2E, -SH2));
    return (SHIFT + __logf(se2)) - zl;
}

// prefetch 8 rows of predict+target into registers
__device__ __forceinline__ void issue_half(const float* __restrict__ predict,
                                           const float* __restrict__ target,
                                           int tile, int rowLocal, int lane,
                                           float4* Vp, float4* Vt)
{
    const size_t base = ((size_t)tile * TM + rowLocal) * 32 + lane;
    const float4* p4 = (const float4*)predict;
    const float4* t4 = (const float4*)target;
    #pragma unroll
    for (int j = 0; j < 8; j++) {
        Vp[j] = __ldg(p4 + base + (size_t)j * 32);
        Vt[j] = __ldg(t4 + base + (size_t)j * 32);
    }
}

// convert+store rows [jlo,jhi) of a prefetched chunk; accumulate ssq, capture label
__device__ __forceinline__ void conv_part(const float4* Vp, const float4* Vt,
                                          char* sAbuf, int rowLocal, int lane, int g,
                                          int jlo, int jhi, float* ssq, int& lbl)
{
    #pragma unroll
    for (int j = 0; j < 8; j++) {
        if (j < jlo || j >= jhi) continue;
        float4 v = Vp[j], t = Vt[j];
        __half2 h0 = __floats2half2_rn(v.x, v.y);
        __half2 h1 = __floats2half2_rn(v.z, v.w);
        unsigned long long pk;
        asm("mov.b64 %0,{%1,%2};" : "=l"(pk)
            : "r"(*(uint32_t*)&h0), "r"(*(uint32_t*)&h1));
        *reinterpret_cast<unsigned long long*>(sAbuf + (rowLocal + j) * 272 + lane * 8) = pk;
        ssq[j] = fmaf(v.x, v.x, fmaf(v.y, v.y, fmaf(v.z, v.z, v.w * v.w)));

        // ballot label: exactly one lane sees the one-hot 1.0 among its 4 values
        bool nz = (t.x > 0.5f) || (t.y > 0.5f) || (t.z > 0.5f) || (t.w > 0.5f);
        unsigned bal = __ballot_sync(0xffffffffu, nz);
        int li = (t.y > 0.5f) ? 1 : ((t.z > 0.5f) ? 2 : ((t.w > 0.5f) ? 3 : 0));
        int src = __ffs(bal) - 1;
        int lblj = 4 * src + __shfl_sync(0xffffffffu, li, src);
        if (j == g) lbl = lblj;
    }
}

// butterfly 8 ssq values -> this lane's row sum (row g)
__device__ __forceinline__ float fold_ssq(float* ssq, int g)
{
    #pragma unroll
    for (int o = 16; o; o >>= 1) {
        #pragma unroll
        for (int i = 0; i < 8; i++) ssq[i] += __shfl_xor_sync(0xffffffffu, ssq[i], o);
    }
    float ss = 0.f;
    #pragma unroll
    for (int i = 0; i < 8; i++) if (i == g) ss = ssq[i];
    return ss;
}

__device__ __forceinline__ void load_afrags(const char* sAbuf, int rb0, int g, int c,
                                            uint32_t* A0, uint32_t* A1,
                                            uint32_t* A2, uint32_t* A3)
{
    const char* a_lo = sAbuf + (rb0 + g) * 272 + c * 4;
    const char* a_hi = a_lo + 8 * 272;
    #pragma unroll
    for (int ks = 0; ks < 8; ks++) {
        A0[ks] = *(const uint32_t*)(a_lo + ks * 32);
        A2[ks] = *(const uint32_t*)(a_lo + ks * 32 + 16);
        A1[ks] = *(const uint32_t*)(a_hi + ks * 32);
        A3[ks] = *(const uint32_t*)(a_hi + ks * 32 + 16);
    }
}

// 4 col-tiles; B via LDS.128 fragment loads (80B lane stride, conflict-free)
__device__ __forceinline__ void mma_quarter(int tstart, const char* sB, int lane, int c,
    const uint32_t* A0, const uint32_t* A1, const uint32_t* A2, const uint32_t* A3,
    float sI0, float sI1, float invn0, float invn1, int lbl0, int lbl1,
    float& ac00, float& ac01, float& ac10, float& ac11, float& cs0, float& cs1)
{
    #pragma unroll
    for (int t = 0; t < 4; t++) {
        const int tt = tstart + t;
        float c0 = 0.f, c1 = 0.f, c2 = 0.f, c3 = 0.f;
        const char* bb = sB + (tt * 32 + lane) * 80;
        #pragma unroll
        for (int q = 0; q < 4; q++) {
            const uint4 bv = *(const uint4*)(bb + q * 16);
            hmma16816(c0, c1, c2, c3,
                      A0[2*q], A1[2*q], A2[2*q], A3[2*q], bv.x, bv.y);
            hmma16816(c0, c1, c2, c3,
                      A0[2*q+1], A1[2*q+1], A2[2*q+1], A3[2*q+1], bv.z, bv.w);
        }
        const int n0 = 8 * tt + 2 * c;
        float e0 = ex2(fmaf(c0, sI0, -SH2));
        float e1 = ex2(fmaf(c1, sI0, -SH2));
        float e2 = ex2(fmaf(c2, sI1, -SH2));
        float e3 = ex2(fmaf(c3, sI1, -SH2));
        if (n0     == lbl0) { cs0 = c0 * invn0; e0 = 0.f; }
        if (n0 + 1 == lbl0) { cs0 = c1 * invn0; e1 = 0.f; }
        if (n0     == lbl1) { cs1 = c2 * invn1; e2 = 0.f; }
        if (n0 + 1 == lbl1) { cs1 = c3 * invn1; e3 = 0.f; }
        ac00 += e0; ac01 += e1; ac10 += e2; ac11 += e3;
    }
}

// ---------------------------------------------------------------------------
// single fused kernel: R12 skeleton + fine-grain mma/convert interleaving
// ---------------------------------------------------------------------------
__global__ void __launch_bounds__(256, 2)
arc_main(const float* __restrict__ predict,
         const float* __restrict__ target,
         const float* __restrict__ weight,
         float* __restrict__ out)
{
    extern __shared__ char sm[];
    char*  sA   = sm + OFF_A;
    char*  sB   = sm + OFF_B;
    float* red  = (float*)(sm + OFF_RED);
    int*   flag = (int*)(sm + OFF_FLAG);

    const int tid  = threadIdx.x;
    const int lane = tid & 31;
    const int w    = tid >> 5;
    const int g    = lane >> 2;
    const int c    = lane & 3;
    const int rb0  = w * 16;
    const int blk  = blockIdx.x;

    // ---- distributed weight prep: CTAs 0..15, one warp per weight row ----
    if (blk < 16) {
        const int row = blk * 8 + w;
        const int gg  = row & 7;
        const int tt  = row >> 3;
        float4 v = reinterpret_cast<const float4*>(weight)[row * 32 + lane];
        float ss = v.x * v.x + v.y * v.y + v.z * v.z + v.w * v.w;
        #pragma unroll
        for (int o = 16; o; o >>= 1) ss += __shfl_xor_sync(0xffffffffu, ss, o);
        float r = 1.0f / fmaxf(sqrtf(ss), 1e-12f);
        __half2 h0 = __floats2half2_rn(v.x * r, v.y * r);   // halves m = 2*lane
        __half2 h1 = __floats2half2_rn(v.z * r, v.w * r);   // halves m = 2*lane+1
        #pragma unroll
        for (int j = 0; j < 2; j++) {
            const int m  = 2 * lane + j;                     // m = k/2 = 8ks+4b+cc
            const int cc = m & 3, b = (m >> 2) & 1, ks = m >> 3;
            const int di = (tt * 32 + gg * 4 + cc) * 16 + 2 * ks + b;
            g_wfrag[di] = (j == 0) ? *(uint32_t*)&h0 : *(uint32_t*)&h1;
        }
        __threadfence();
        __syncthreads();
        if (tid == 0) atomicAdd(&g_ready, 1);
    }

    float4 Vp[8], Vt[8];
    uint32_t A0[8], A1[8], A2[8], A3[8];

    // ---- first tile prologue (no B dependence) ----
    int tile = blk;
    float ss0, ss1; int lbl0 = 0, lbl1 = 0;
    {
        float ssq[8];
        issue_half(predict, target, tile, rb0, lane, Vp, Vt);
        conv_part(Vp, Vt, sA, rb0, lane, g, 0, 8, ssq, lbl0);
        ss0 = fold_ssq(ssq, g);
        issue_half(predict, target, tile, rb0 + 8, lane, Vp, Vt);
        conv_part(Vp, Vt, sA, rb0 + 8, lane, g, 0, 8, ssq, lbl1);
        ss1 = fold_ssq(ssq, g);
    }
    __syncwarp();
    load_afrags(sA, rb0, g, c, A0, A1, A2, A3);
    float invn0 = rsqrtf(fmaxf(ss0, 1e-24f));
    float invn1 = rsqrtf(fmaxf(ss1, 1e-24f));

    int  next    = tile + NPERS;
    bool hasNext = next < NTILES;
    if (hasNext) issue_half(predict, target, next, rb0, lane, Vp, Vt);

    // ---- wait for weight prep, then stage B (spin hidden by prologue) ----
    if (tid == 0) { while (atomicAdd(&g_ready, 0) < 16) { } }
    __syncthreads();
    {
        const uint4* gw = (const uint4*)g_wfrag;    // 2048 uint4
        #pragma unroll
        for (int i = 0; i < 8; i++) {
            int idx = i * 256 + tid;
            *(uint4*)(sB + (idx >> 2) * 80 + (idx & 3) * 16) = gw[idx];
        }
    }
    __syncthreads();

    float nll_acc = 0.f;
    float ns0 = 0.f, ns1 = 0.f; int nl0 = 0, nl1 = 0;

    while (true) {
        const float sI0 = Sv * invn0 * LOG2E, sI1 = Sv * invn1 * LOG2E;
        float ac00 = 0.f, ac01 = 0.f, ac10 = 0.f, ac11 = 0.f;
        float cs0 = -2.0f, cs1 = -2.0f;
        float ssq[8];

        // ---- interleaved: mma quarters <-> convert pieces (in-order issue) ----
        mma_quarter(0, sB, lane, c, A0, A1, A2, A3, sI0, sI1, invn0, invn1,
                    lbl0, lbl1, ac00, ac01, ac10, ac11, cs0, cs1);
        if (hasNext)
            conv_part(Vp, Vt, sA, rb0, lane, g, 0, 4, ssq, nl0);   // h0 rows 0-3

        mma_quarter(4, sB, lane, c, A0, A1, A2, A3, sI0, sI1, invn0, invn1,
                    lbl0, lbl1, ac00, ac01, ac10, ac11, cs0, cs1);
        if (hasNext) {
            conv_part(Vp, Vt, sA, rb0, lane, g, 4, 8, ssq, nl0);   // h0 rows 4-7
            ns0 = fold_ssq(ssq, g);
            issue_half(predict, target, next, rb0 + 8, lane, Vp, Vt);
        }

        mma_quarter(8, sB, lane, c, A0, A1, A2, A3, sI0, sI1, invn0, invn1,
                    lbl0, lbl1, ac00, ac01, ac10, ac11, cs0, cs1);
        mma_quarter(12, sB, lane, c, A0, A1, A2, A3, sI0, sI1, invn0, invn1,
                    lbl0, lbl1, ac00, ac01, ac10, ac11, cs0, cs1);

        // ---- tile epilogue ----
        float se0 = ac00 + ac01, se1 = ac10 + ac11;
        se0 += __shfl_xor_sync(0xffffffffu, se0, 1);
        se0 += __shfl_xor_sync(0xffffffffu, se0, 2);
        se1 += __shfl_xor_sync(0xffffffffu, se1, 1);
        se1 += __shfl_xor_sync(0xffffffffu, se1, 2);
        cs0 = fmaxf(cs0, __shfl_xor_sync(0xffffffffu, cs0, 1));
        cs0 = fmaxf(cs0, __shfl_xor_sync(0xffffffffu, cs0, 2));
        cs1 = fmaxf(cs1, __shfl_xor_sync(0xffffffffu, cs1, 1));
        cs1 = fmaxf(cs1, __shfl_xor_sync(0xffffffffu, cs1, 2));
        if (c == 0) nll_acc += row_nll(se0, cs0) + row_nll(se1, cs1);

        if (!hasNext) break;

        conv_part(Vp, Vt, sA, rb0 + 8, lane, g, 0, 8, ssq, nl1);   // h1 rows
        ns1 = fold_ssq(ssq, g);
        __syncwarp();
        load_afrags(sA, rb0, g, c, A0, A1, A2, A3);
        invn0 = rsqrtf(fmaxf(ns0, 1e-24f));
        invn1 = rsqrtf(fmaxf(ns1, 1e-24f));
        lbl0 = nl0; lbl1 = nl1;

        tile = next; next += NPERS; hasNext = next < NTILES;
        if (hasNext) issue_half(predict, target, next, rb0, lane, Vp, Vt);
    }

    // ---- warp & block reduction of accumulated NLL ----
    float nll = nll_acc;
    #pragma unroll
    for (int o = 16; o; o >>= 1) nll += __shfl_xor_sync(0xffffffffu, nll, o);
    if (lane == 0) red[w] = nll;
    __syncthreads();

    if (tid == 0) {
        float t = 0.0f;
        #pragma unroll
        for (int i = 0; i < 8; i++) t += red[i];
        g_bsum[blk] = t;
        __threadfence();
        int cdone = atomicAdd(&g_cnt, 1);
        *flag = (cdone == NPERS - 1) ? 1 : 0;
    }
    __syncthreads();

    // last CTA: deterministic final reduction -> mean; reset counters
    if (*flag) {
        __threadfence();
        float t = g_bsum[tid];
        if (tid + 256 < NPERS) t += g_bsum[tid + 256];
        float* fr = (float*)sA;   // reuse smem
        fr[tid] = t;
        __syncthreads();
        #pragma unroll
        for (int st = 128; st; st >>= 1) {
            if (tid < st) fr[tid] += fr[tid + st];
            __syncthreads();
        }
        if (tid == 0) {
            out[0]  = fr[0] / (float)Bn;
            g_cnt   = 0;
            g_ready = 0;
        }
    }
}

// ---------------------------------------------------------------------------
extern "C" void kernel_launch(void* const* d_in, const int* in_sizes, int n_in,
                              void* d_out, int out_size)
{
    (void)in_sizes; (void)n_in; (void)out_size;
    const float* predict = (const float*)d_in[0];
    const float* target  = (const float*)d_in[1];
    const float* weight  = (const float*)d_in[2];

    cudaFuncSetAttribute(arc_main, cudaFuncAttributeMaxDynamicSharedMemorySize, SMEM_SZ);

    arc_main<<<NPERS, 256, SMEM_SZ>>>(predict, target, weight, (float*)d_out);
}

// round 17
// speedup vs baseline: 2.4100x; 1.0811x over previous
#include <cuda_runtime.h>
#include <cuda_fp16.h>
#include <cstdint>

// Problem constants
#define Bn 131072
#define Cn 128
#define En 128
#define TM 128              // samples per tile
#define NTILES (Bn / TM)    // 1024
#define NPERS 296           // persistent CTAs (2 per SM on 148 SMs)

// ArcFace constants (m = 1.0, s = 100)
#define COSM 0.5403023058681398f
#define SINM 0.8414709848078965f
#define THv  (-0.5403023058681398f)
#define MMv  0.8414709848078965f
#define Sv   100.0f
#define SHIFT 30.0f
#define LOG2E 1.4426950408889634f
#define SH2   (SHIFT * LOG2E)

// Scratch (no allocation allowed -> device globals)
__device__ uint32_t g_wfrag[8192];   // 32KB: normalized weight fp16, fragment order
__device__ float    g_bsum[NPERS];
__device__ int      g_cnt;           // zero-init; reset by last CTA each launch
__device__ int      g_ready;         // weight-prep release counter (16 CTAs)

// smem layout (no A buffer anymore)
#define OFF_B    0                   // B fragments, 512 lane-rows x 80B -> 40960
#define OFF_T    40960               // target staging: 8 warps x 8 rows x 512B -> 32768
#define OFF_RED  73728               // float[8]
#define OFF_FLAG 73760               // int
#define SMEM_SZ  73792

__device__ __forceinline__ float ex2(float x) {
    float r; asm("ex2.approx.f32 %0, %1;" : "=f"(r) : "f"(x)); return r;
}
__device__ __forceinline__ uint32_t smem_u32(const void* p) {
    uint32_t a;
    asm("{ .reg .u64 t; cvta.to.shared.u64 t, %1; cvt.u32.u64 %0, t; }"
        : "=r"(a) : "l"(p));
    return a;
}
__device__ __forceinline__ uint32_t packh2(float x, float y) {
    __half2 h = __floats2half2_rn(x, y);
    return *(uint32_t*)&h;
}

__device__ __forceinline__ void hmma16816(float& c0, float& c1, float& c2, float& c3,
                                          uint32_t a0, uint32_t a1, uint32_t a2, uint32_t a3,
                                          uint32_t b0, uint32_t b1) {
    asm volatile(
        "mma.sync.aligned.m16n8k16.row.col.f32.f16.f16.f32 "
        "{%0,%1,%2,%3}, {%4,%5,%6,%7}, {%8,%9}, {%0,%1,%2,%3};"
        : "+f"(c0), "+f"(c1), "+f"(c2), "+f"(c3)
        : "r"(a0), "r"(a1), "r"(a2), "r"(a3), "r"(b0), "r"(b1));
}

// NLL from label-EXCLUDED shifted sum se = sum exp(z-30), and label cosine cs.
__device__ __forceinline__ float row_nll(float se, float cs) {
    float sn  = sqrtf(fmaxf(1.0f - cs * cs, 0.0f));
    float phi = (cs > THv) ? (cs * COSM - sn * SINM) : (cs - MMv);
    float zl  = Sv * phi;
    float se2 = se + ex2(fmaf(zl, LOG2E, -SH2));
    return (SHIFT + __logf(se2)) - zl;
}

// direct fragment loads: lane (g,c) reads its float2 fragment sources for
// rows rb0+g and rb0+8+g; uhalf selects u=0..7 (ks 0..3) or u=8..15 (ks 4..7)
__device__ __forceinline__ void issue_pred(const float* __restrict__ predict,
                                           int tile, int rb0, int g, int c, int uhalf,
                                           float2* P0, float2* P1)
{
    const float2* r0 = (const float2*)(predict + (size_t)(tile * TM + rb0 + g) * En)
                       + uhalf * 32 + c;
    const float2* r1 = r0 + 8 * (En / 2);     // row +8
    #pragma unroll
    for (int i = 0; i < 8; i++) {
        P0[i] = __ldg(r0 + 4 * i);
        P1[i] = __ldg(r1 + 4 * i);
    }
}

// cp.async 8 target rows (16B per lane per row) into this warp's staging slice
__device__ __forceinline__ void issue_tgt(const float* __restrict__ target,
                                          int tile, int rowLocal, int lane, uint32_t tb)
{
    const float* src = target + (size_t)(tile * TM + rowLocal) * En + lane * 4;
    #pragma unroll
    for (int j = 0; j < 8; j++) {
        asm volatile("cp.async.cg.shared.global [%0], [%1], 16;"
                     :: "r"(tb + j * 512 + lane * 16), "l"(src + (size_t)j * En)
                     : "memory");
    }
    asm volatile("cp.async.commit_group;" ::: "memory");
}

// wait + ballot labels for 8 staged rows; return label of local row j==g
__device__ __forceinline__ int consume_tgt(const char* tslice, int lane, int g)
{
    asm volatile("cp.async.wait_group 0;" ::: "memory");
    int lbl = 0;
    #pragma unroll
    for (int j = 0; j < 8; j++) {
        float4 t = *(const float4*)(tslice + j * 512 + lane * 16);
        bool nz = (t.x > 0.5f) || (t.y > 0.5f) || (t.z > 0.5f) || (t.w > 0.5f);
        unsigned bal = __ballot_sync(0xffffffffu, nz);
        int li = (t.y > 0.5f) ? 1 : ((t.z > 0.5f) ? 2 : ((t.w > 0.5f) ? 3 : 0));
        int src = __ffs(bal) - 1;
        int lblj = 4 * src + __shfl_sync(0xffffffffu, li, src);
        if (j == g) lbl = lblj;
    }
    return lbl;
}

// convert one prefetched half (u = 4q.. ) into fragment regs + ssq accumulate
__device__ __forceinline__ void conv_half(const float2* P0, const float2* P1, int qb,
                                          uint32_t* A0, uint32_t* A1,
                                          uint32_t* A2, uint32_t* A3,
                                          float& ss0, float& ss1)
{
    #pragma unroll
    for (int q = 0; q < 4; q++) {
        float2 a = P0[2*q], b = P0[2*q+1];
        float2 e = P1[2*q], f = P1[2*q+1];
        A0[qb + q] = packh2(a.x, a.y);
        A2[qb + q] = packh2(b.x, b.y);
        A1[qb + q] = packh2(e.x, e.y);
        A3[qb + q] = packh2(f.x, f.y);
        ss0 = fmaf(a.x, a.x, fmaf(a.y, a.y, fmaf(b.x, b.x, fmaf(b.y, b.y, ss0))));
        ss1 = fmaf(e.x, e.x, fmaf(e.y, e.y, fmaf(f.x, f.x, fmaf(f.y, f.y, ss1))));
    }
}

// 8 col-tiles; B via LDS.128 fragment loads (80B lane stride, conflict-free)
__device__ __forceinline__ void mma_half(int tstart, const char* sB, int lane, int c,
    const uint32_t* A0, const uint32_t* A1, const uint32_t* A2, const uint32_t* A3,
    float sI0, float sI1, float invn0, float invn1, int lbl0, int lbl1,
    float& ac00, float& ac01, float& ac10, float& ac11, float& cs0, float& cs1)
{
    #pragma unroll
    for (int t = 0; t < 8; t++) {
        const int tt = tstart + t;
        float c0 = 0.f, c1 = 0.f, c2 = 0.f, c3 = 0.f;
        const char* bb = sB + (tt * 32 + lane) * 80;
        #pragma unroll
        for (int q = 0; q < 4; q++) {
            const uint4 bv = *(const uint4*)(bb + q * 16);
            hmma16816(c0, c1, c2, c3,
                      A0[2*q], A1[2*q], A2[2*q], A3[2*q], bv.x, bv.y);
            hmma16816(c0, c1, c2, c3,
                      A0[2*q+1], A1[2*q+1], A2[2*q+1], A3[2*q+1], bv.z, bv.w);
        }
        const int n0 = 8 * tt + 2 * c;
        float e0 = ex2(fmaf(c0, sI0, -SH2));
        float e1 = ex2(fmaf(c1, sI0, -SH2));
        float e2 = ex2(fmaf(c2, sI1, -SH2));
        float e3 = ex2(fmaf(c3, sI1, -SH2));
        if (n0     == lbl0) { cs0 = c0 * invn0; e0 = 0.f; }
        if (n0 + 1 == lbl0) { cs0 = c1 * invn0; e1 = 0.f; }
        if (n0     == lbl1) { cs1 = c2 * invn1; e2 = 0.f; }
        if (n0 + 1 == lbl1) { cs1 = c3 * invn1; e3 = 0.f; }
        ac00 += e0; ac01 += e1; ac10 += e2; ac11 += e3;
    }
}

// ---------------------------------------------------------------------------
// fused kernel: direct-fragment predict loads (no A smem), cp.async target
// ---------------------------------------------------------------------------
__global__ void __launch_bounds__(256, 2)
arc_main(const float* __restrict__ predict,
         const float* __restrict__ target,
         const float* __restrict__ weight,
         float* __restrict__ out)
{
    extern __shared__ char sm[];
    char*  sB   = sm + OFF_B;
    float* red  = (float*)(sm + OFF_RED);
    int*   flag = (int*)(sm + OFF_FLAG);

    const int tid  = threadIdx.x;
    const int lane = tid & 31;
    const int w    = tid >> 5;
    const int g    = lane >> 2;
    const int c    = lane & 3;
    const int rb0  = w * 16;
    const int blk  = blockIdx.x;

    char*          tslice = sm + OFF_T + w * 4096;
    const uint32_t tb     = smem_u32(sm) + OFF_T + w * 4096;

    // ---- distributed weight prep: CTAs 0..15, one warp per weight row ----
    if (blk < 16) {
        const int row = blk * 8 + w;
        const int gg  = row & 7;
        const int tt  = row >> 3;
        float4 v = reinterpret_cast<const float4*>(weight)[row * 32 + lane];
        float ss = v.x * v.x + v.y * v.y + v.z * v.z + v.w * v.w;
        #pragma unroll
        for (int o = 16; o; o >>= 1) ss += __shfl_xor_sync(0xffffffffu, ss, o);
        float r = 1.0f / fmaxf(sqrtf(ss), 1e-12f);
        uint32_t h0 = packh2(v.x * r, v.y * r);   // halves m = 2*lane
        uint32_t h1 = packh2(v.z * r, v.w * r);   // halves m = 2*lane+1
        #pragma unroll
        for (int j = 0; j < 2; j++) {
            const int m  = 2 * lane + j;           // m = k/2 = 8ks+4b+cc
            const int cc = m & 3, b = (m >> 2) & 1, ks = m >> 3;
            const int di = (tt * 32 + gg * 4 + cc) * 16 + 2 * ks + b;
            g_wfrag[di] = (j == 0) ? h0 : h1;
        }
        __threadfence();
        __syncthreads();
        if (tid == 0) atomicAdd(&g_ready, 1);
    }

    float2   P0[8], P1[8];
    uint32_t A0[8], A1[8], A2[8], A3[8];
    uint32_t N0[8], N1[8], N2[8], N3[8];

    // ---- first tile prologue (no B dependence) ----
    int tile = blk;
    float ss0 = 0.f, ss1 = 0.f;
    int lbl0 = 0, lbl1 = 0;

    issue_pred(predict, tile, rb0, g, c, 0, P0, P1);
    issue_tgt(target, tile, rb0, lane, tb);
    conv_half(P0, P1, 0, A0, A1, A2, A3, ss0, ss1);
    issue_pred(predict, tile, rb0, g, c, 1, P0, P1);
    lbl0 = consume_tgt(tslice, lane, g);
    issue_tgt(target, tile, rb0 + 8, lane, tb);
    conv_half(P0, P1, 4, A0, A1, A2, A3, ss0, ss1);
    lbl1 = consume_tgt(tslice, lane, g);

    ss0 += __shfl_xor_sync(0xffffffffu, ss0, 1);
    ss0 += __shfl_xor_sync(0xffffffffu, ss0, 2);
    ss1 += __shfl_xor_sync(0xffffffffu, ss1, 1);
    ss1 += __shfl_xor_sync(0xffffffffu, ss1, 2);
    float invn0 = rsqrtf(fmaxf(ss0, 1e-24f));
    float invn1 = rsqrtf(fmaxf(ss1, 1e-24f));

    int  next    = tile + NPERS;
    bool hasNext = next < NTILES;
    if (hasNext) {
        issue_pred(predict, next, rb0, g, c, 0, P0, P1);
        issue_tgt(target, next, rb0, lane, tb);
    }

    // ---- wait for weight prep, then stage B (spin hidden by prologue) ----
    if (tid == 0) { while (atomicAdd(&g_ready, 0) < 16) { } }
    __syncthreads();
    {
        const uint4* gw = (const uint4*)g_wfrag;    // 2048 uint4
        #pragma unroll
        for (int i = 0; i < 8; i++) {
            int idx = i * 256 + tid;
            *(uint4*)(sB + (idx >> 2) * 80 + (idx & 3) * 16) = gw[idx];
        }
    }
    __syncthreads();

    float nll_acc = 0.f;
    int nl0 = 0, nl1 = 0;

    while (true) {
        const float sI0 = Sv * invn0 * LOG2E, sI1 = Sv * invn1 * LOG2E;
        float ac00 = 0.f, ac01 = 0.f, ac10 = 0.f, ac11 = 0.f;
        float cs0 = -2.0f, cs1 = -2.0f;
        float ns0 = 0.f, ns1 = 0.f;

        mma_half(0, sB, lane, c, A0, A1, A2, A3, sI0, sI1, invn0, invn1, lbl0, lbl1,
                 ac00, ac01, ac10, ac11, cs0, cs1);

        if (hasNext) {
            conv_half(P0, P1, 0, N0, N1, N2, N3, ns0, ns1);
            nl0 = consume_tgt(tslice, lane, g);
            issue_pred(predict, next, rb0, g, c, 1, P0, P1);
            issue_tgt(target, next, rb0 + 8, lane, tb);
        }

        mma_half(8, sB, lane, c, A0, A1, A2, A3, sI0, sI1, invn0, invn1, lbl0, lbl1,
                 ac00, ac01, ac10, ac11, cs0, cs1);

        if (hasNext) {
            conv_half(P0, P1, 4, N0, N1, N2, N3, ns0, ns1);
            nl1 = consume_tgt(tslice, lane, g);
        }

        // ---- tile epilogue ----
        float se0 = ac00 + ac01, se1 = ac10 + ac11;
        se0 += __shfl_xor_sync(0xffffffffu, se0, 1);
        se0 += __shfl_xor_sync(0xffffffffu, se0, 2);
        se1 += __shfl_xor_sync(0xffffffffu, se1, 1);
        se1 += __shfl_xor_sync(0xffffffffu, se1, 2);
        cs0 = fmaxf(cs0, __shfl_xor_sync(0xffffffffu, cs0, 1));
        cs0 = fmaxf(cs0, __shfl_xor_sync(0xffffffffu, cs0, 2));
        cs1 = fmaxf(cs1, __shfl_xor_sync(0xffffffffu, cs1, 1));
        cs1 = fmaxf(cs1, __shfl_xor_sync(0xffffffffu, cs1, 2));
        if (c == 0) nll_acc += row_nll(se0, cs0) + row_nll(se1, cs1);

        if (!hasNext) break;

        // promote next-tile state
        ns0 += __shfl_xor_sync(0xffffffffu, ns0, 1);
        ns0 += __shfl_xor_sync(0xffffffffu, ns0, 2);
        ns1 += __shfl_xor_sync(0xffffffffu, ns1, 1);
        ns1 += __shfl_xor_sync(0xffffffffu, ns1, 2);
        invn0 = rsqrtf(fmaxf(ns0, 1e-24f));
        invn1 = rsqrtf(fmaxf(ns1, 1e-24f));
        lbl0 = nl0; lbl1 = nl1;
        #pragma unroll
        for (int i = 0; i < 8; i++) {
            A0[i] = N0[i]; A1[i] = N1[i]; A2[i] = N2[i]; A3[i] = N3[i];
        }

        tile = next; next += NPERS; hasNext = next < NTILES;
        if (hasNext) {
            issue_pred(predict, next, rb0, g, c, 0, P0, P1);
            issue_tgt(target, next, rb0, lane, tb);
        }
    }

    // ---- warp & block reduction of accumulated NLL ----
    float nll = nll_acc;
    #pragma unroll
    for (int o = 16; o; o >>= 1) nll += __shfl_xor_sync(0xffffffffu, nll, o);
    if (lane == 0) red[w] = nll;
    __syncthreads();

    if (tid == 0) {
        float t = 0.0f;
        #pragma unroll
        for (int i = 0; i < 8; i++) t += red[i];
        g_bsum[blk] = t;
        __threadfence();
        int cdone = atomicAdd(&g_cnt, 1);
        *flag = (cdone == NPERS - 1) ? 1 : 0;
    }
    __syncthreads();

    // last CTA: deterministic final reduction -> mean; reset counters
    if (*flag) {
        __threadfence();
        float t = g_bsum[tid];
        if (tid + 256 < NPERS) t += g_bsum[tid + 256];
        float* fr = (float*)sm;   // reuse smem
        fr[tid] = t;
        __syncthreads();
        #pragma unroll
        for (int st = 128; st; st >>= 1) {
            if (tid < st) fr[tid] += fr[tid + st];
            __syncthreads();
        }
        if (tid == 0) {
            out[0]  = fr[0] / (float)Bn;
            g_cnt   = 0;
            g_ready = 0;
        }
    }
}

// ---------------------------------------------------------------------------
extern "C" void kernel_launch(void* const* d_in, const int* in_sizes, int n_in,
                              void* d_out, int out_size)
{
    (void)in_sizes; (void)n_in; (void)out_size;
    const float* predict = (const float*)d_in[0];
    const float* target  = (const float*)d_in[1];
    const float* weight  = (const float*)d_in[2];

    cudaFuncSetAttribute(arc_main, cudaFuncAttributeMaxDynamicSharedMemorySize, SMEM_SZ);

    arc_main<<<NPERS, 256, SMEM_SZ>>>(predict, target, weight, (float*)d_out);
}